// round 16
// baseline (speedup 1.0000x reference)
#include <cuda_runtime.h>
#include <cuda_bf16.h>
#include <cuda_fp16.h>
#include <cmath>
#include <cstdint>

typedef __nv_bfloat16 bf16;

// ---------------- problem constants ----------------
#define NWIN   8192
#define TTOK   401408
#define HWI    224
#define HWSQ   50176
#define DIMC   192

// scratch (allocation-free static device arrays)
__device__ __half g_qkvh [(size_t)TTOK * 576];   // QKV (scaled/biased, fp16)
__device__ __half g_attnh[(size_t)TTOK * DIMC];  // attention out (fp16)
__device__ float  g_h1  [(size_t)TTOK * DIMC];   // x + attn branch (fp32)
__device__ float  g_bias [6 * 49 * 49];

// pre-packed B fragments (mma.sync m16n8k16 layout), one uint4 per lane per 16x16 tile
#define N_QKVP  (36 * 12 * 32)
#define N_PROJP (12 * 12 * 32)
#define N_FC1P  (48 * 12 * 32)
#define N_FC2P  (12 * 48 * 32)
__device__ uint4 g_qkvp [N_QKVP];
__device__ uint4 g_projp[N_PROJP];
__device__ uint4 g_fc1p [N_FC1P];
__device__ uint4 g_fc2p [N_FC2P];

// ---------------- mma.sync helpers ----------------
__device__ __forceinline__ uint32_t smem_u32(const void* p) {
    uint32_t a;
    asm("{ .reg .u64 t; cvta.to.shared.u64 t, %1; cvt.u32.u64 %0, t; }" : "=r"(a) : "l"(p));
    return a;
}
__device__ __forceinline__ void ldsm_x4(uint32_t (&r)[4], uint32_t addr) {
    asm volatile("ldmatrix.sync.aligned.m8n8.x4.shared.b16 {%0,%1,%2,%3}, [%4];"
        : "=r"(r[0]), "=r"(r[1]), "=r"(r[2]), "=r"(r[3]) : "r"(addr));
}
__device__ __forceinline__ void ldsm_x4_t(uint32_t (&r)[4], uint32_t addr) {
    asm volatile("ldmatrix.sync.aligned.m8n8.x4.trans.shared.b16 {%0,%1,%2,%3}, [%4];"
        : "=r"(r[0]), "=r"(r[1]), "=r"(r[2]), "=r"(r[3]) : "r"(addr));
}
__device__ __forceinline__ void mma_h(float (&c)[4], const uint32_t (&a)[4], uint32_t b0, uint32_t b1) {
    asm volatile("mma.sync.aligned.m16n8k16.row.col.f32.f16.f16.f32 "
        "{%0,%1,%2,%3},{%4,%5,%6,%7},{%8,%9},{%0,%1,%2,%3};"
        : "+f"(c[0]), "+f"(c[1]), "+f"(c[2]), "+f"(c[3])
        : "r"(a[0]), "r"(a[1]), "r"(a[2]), "r"(a[3]), "r"(b0), "r"(b1));
}
__device__ __forceinline__ void mma_b(float (&c)[4], const uint32_t (&a)[4], uint32_t b0, uint32_t b1) {
    asm volatile("mma.sync.aligned.m16n8k16.row.col.f32.bf16.bf16.f32 "
        "{%0,%1,%2,%3},{%4,%5,%6,%7},{%8,%9},{%0,%1,%2,%3};"
        : "+f"(c[0]), "+f"(c[1]), "+f"(c[2]), "+f"(c[3])
        : "r"(a[0]), "r"(a[1]), "r"(a[2]), "r"(a[3]), "r"(b0), "r"(b1));
}

__device__ __forceinline__ uint32_t pack_h2(float x, float y) {
    __half2 h = __floats2half2_rn(x, y); return *(uint32_t*)&h;
}
__device__ __forceinline__ uint32_t pack_b2(float x, float y) {
    __nv_bfloat162 h = __floats2bfloat162_rn(x, y); return *(uint32_t*)&h;
}
__device__ __forceinline__ uint4 pack_tile_h(const float* W, int N, int K0, int N0, int lane) {
    int g = lane >> 2, tig = lane & 3;
    int k0 = K0 + tig * 2;
    uint4 u;
    u.x = pack_h2(W[(size_t)k0 * N + N0 + g],       W[(size_t)(k0 + 1) * N + N0 + g]);
    u.y = pack_h2(W[(size_t)(k0 + 8) * N + N0 + g], W[(size_t)(k0 + 9) * N + N0 + g]);
    u.z = pack_h2(W[(size_t)k0 * N + N0 + 8 + g],       W[(size_t)(k0 + 1) * N + N0 + 8 + g]);
    u.w = pack_h2(W[(size_t)(k0 + 8) * N + N0 + 8 + g], W[(size_t)(k0 + 9) * N + N0 + 8 + g]);
    return u;
}
__device__ __forceinline__ uint4 pack_tile_b(const float* W, int N, int K0, int N0, int lane) {
    int g = lane >> 2, tig = lane & 3;
    int k0 = K0 + tig * 2;
    uint4 u;
    u.x = pack_b2(W[(size_t)k0 * N + N0 + g],       W[(size_t)(k0 + 1) * N + N0 + g]);
    u.y = pack_b2(W[(size_t)(k0 + 8) * N + N0 + g], W[(size_t)(k0 + 9) * N + N0 + g]);
    u.z = pack_b2(W[(size_t)k0 * N + N0 + 8 + g],       W[(size_t)(k0 + 1) * N + N0 + 8 + g]);
    u.w = pack_b2(W[(size_t)(k0 + 8) * N + N0 + 8 + g], W[(size_t)(k0 + 9) * N + N0 + 8 + g]);
    return u;
}

// ---------------- prelude: pack weights + bias table ----------------
#define N_BIAS 14406
#define PRE_TOT (N_QKVP + N_PROJP + N_FC1P + N_FC2P + N_BIAS)

__global__ void prelude(const float* __restrict__ qkvw, const float* __restrict__ projw,
                        const float* __restrict__ fc1w, const float* __restrict__ fc2w,
                        const float* __restrict__ rpb,  const int* __restrict__ relidx)
{
    int i = blockIdx.x * blockDim.x + threadIdx.x;
    if (i < N_QKVP) {
        int lane = i & 31, t = i >> 5, T = t / 12, K = t - T * 12;
        g_qkvp[i] = pack_tile_h(qkvw, 576, K * 16, T * 16, lane); return;
    }
    i -= N_QKVP;
    if (i < N_PROJP) {
        int lane = i & 31, t = i >> 5, T = t / 12, K = t - T * 12;
        g_projp[i] = pack_tile_h(projw, 192, K * 16, T * 16, lane); return;
    }
    i -= N_PROJP;
    if (i < N_FC1P) {
        int lane = i & 31, t = i >> 5, T = t / 12, K = t - T * 12;
        g_fc1p[i] = pack_tile_b(fc1w, 768, K * 16, T * 16, lane); return;
    }
    i -= N_FC1P;
    if (i < N_FC2P) {
        int lane = i & 31, t = i >> 5, T = t / 48, K = t - T * 48;
        g_fc2p[i] = pack_tile_b(fc2w, 192, K * 16, T * 16, lane); return;
    }
    i -= N_FC2P;
    if (i < N_BIAS) {
        int h = i / 2401, rj = i - h * 2401;
        g_bias[i] = rpb[relidx[rj] * 6 + h];
    }
}

// ============================================================================
// Kernel A: batched QKV GEMM, fp16 mma.sync (6272 CTAs, 256 thr, 2 CTAs/SM)
// ============================================================================
#define XN_LD 196
#define XH_LD 200
#define ST_LD 196
#define QKV_SMEM 75776

__global__ void __launch_bounds__(256, 2)
qkv_gemm(const float* __restrict__ x,
         const float* __restrict__ ln1w, const float* __restrict__ ln1b,
         const float* __restrict__ qkvb)
{
    extern __shared__ char smc[];
    float*  xnf = (float*)smc;
    float*  st  = (float*)smc;                 // overlay (used after LN1)
    __half* xh  = (__half*)(smc + 50176);

    const int tid  = threadIdx.x;
    const int wid  = tid >> 5;
    const int lane = tid & 31;
    const int t0   = blockIdx.x * 64;

    // gather x (fp32)
    {
        const int r = tid & 63;
        const int t = t0 + r;
        const int win = t / 49, pos = t - win * 49;
        const int b = win >> 10, wh = (win >> 5) & 31, ww = win & 31;
        const int pi = pos / 7;
        const float* src = x + (size_t)b * DIMC * HWSQ + (wh * 7 + pi) * HWI + (ww * 7 + pos - pi * 7);
        for (int c = tid >> 6; c < DIMC; c += 4)
            xnf[r * XN_LD + c] = src[(size_t)c * HWSQ];
    }
    __syncthreads();

    // LN1 (fp32 stats) -> fp16 A operand
    for (int r = wid; r < 64; r += 8) {
        float v[6]; float s = 0.f;
#pragma unroll
        for (int q = 0; q < 6; q++) { v[q] = xnf[r * XN_LD + lane + q * 32]; s += v[q]; }
#pragma unroll
        for (int o = 16; o; o >>= 1) s += __shfl_xor_sync(~0u, s, o);
        float mu = s * (1.f / 192.f);
        float vs = 0.f;
#pragma unroll
        for (int q = 0; q < 6; q++) { float d = v[q] - mu; vs += d * d; }
#pragma unroll
        for (int o = 16; o; o >>= 1) vs += __shfl_xor_sync(~0u, vs, o);
        float rs = rsqrtf(vs * (1.f / 192.f) + 1e-5f);
#pragma unroll
        for (int q = 0; q < 6; q++) {
            int c = lane + q * 32;
            xh[r * XH_LD + c] = __float2half_rn((v[q] - mu) * rs * ln1w[c] + ln1b[c]);
        }
    }
    __syncthreads();

    const int rtg = wid & 1;
    const int ctg = wid >> 1;
    const int gg = lane >> 2, tig = lane & 3;
    const float scale = 0.17677669529663687f;

    // hoisted per-thread A base address (bytes): row = rtg*32+(lane&15), col=(lane>>4)*8
    const uint32_t abase = smem_u32(xh) +
        (((rtg * 32 + (lane & 15)) * XH_LD + ((lane >> 4) << 3)) << 1);
    const uint32_t arow16 = (16 * XH_LD) << 1;   // +16 rows in bytes

    for (int chunk = 0; chunk < 3; chunk++) {
        float acc[2][3][2][4];
#pragma unroll
        for (int i = 0; i < 2; i++)
#pragma unroll
            for (int j = 0; j < 3; j++)
#pragma unroll
                for (int p = 0; p < 2; p++)
#pragma unroll
                    for (int q = 0; q < 4; q++) acc[i][j][p][q] = 0.f;

        uint4 wb[3];
#pragma unroll
        for (int j = 0; j < 3; j++)
            wb[j] = g_qkvp[((size_t)(chunk * 12 + ctg * 3 + j) * 12) * 32 + lane];

        for (int k = 0; k < 12; k++) {
            uint4 nb[3];
            if (k < 11) {
#pragma unroll
                for (int j = 0; j < 3; j++)
                    nb[j] = g_qkvp[((size_t)(chunk * 12 + ctg * 3 + j) * 12 + k + 1) * 32 + lane];
            }
            uint32_t RA[2][4];
#pragma unroll
            for (int i = 0; i < 2; i++)
                ldsm_x4(RA[i], abase + i * arow16 + k * 32);
#pragma unroll
            for (int j = 0; j < 3; j++)
#pragma unroll
                for (int i = 0; i < 2; i++) {
                    mma_h(acc[i][j][0], RA[i], wb[j].x, wb[j].y);
                    mma_h(acc[i][j][1], RA[i], wb[j].z, wb[j].w);
                }
            if (k < 11) { wb[0] = nb[0]; wb[1] = nb[1]; wb[2] = nb[2]; }
        }
#pragma unroll
        for (int i = 0; i < 2; i++)
#pragma unroll
            for (int j = 0; j < 3; j++)
#pragma unroll
                for (int p = 0; p < 2; p++) {
                    int col = (ctg * 3 + j) * 16 + p * 8 + tig * 2;
                    int row = rtg * 32 + i * 16 + gg;
                    *(float2*)(st + row * ST_LD + col)       = make_float2(acc[i][j][p][0], acc[i][j][p][1]);
                    *(float2*)(st + (row + 8) * ST_LD + col) = make_float2(acc[i][j][p][2], acc[i][j][p][3]);
                }
        __syncthreads();

        {
            const float sc = (chunk == 0) ? scale : 1.f;
            for (int idx = tid; idx < 64 * 48; idx += 256) {
                int r = idx / 48, c4 = (idx - r * 48) * 4;
                int gc = chunk * 192 + c4;
                float4 v  = *(const float4*)(st + r * ST_LD + c4);
                float4 bb = *(const float4*)(qkvb + gc);
                __half2 h0 = __floats2half2_rn((v.x + bb.x) * sc, (v.y + bb.y) * sc);
                __half2 h1 = __floats2half2_rn((v.z + bb.z) * sc, (v.w + bb.w) * sc);
                uint2 u; u.x = *(uint32_t*)&h0; u.y = *(uint32_t*)&h1;
                *(uint2*)(g_qkvh + (size_t)(t0 + r) * 576 + gc) = u;
            }
        }
        __syncthreads();
    }
}

// ============================================================================
// Kernel B: per window-head attention, fp16 mma.sync (grid (NWIN,6), 128 thr)
// smem: qs/ks/vs half[64][40]; pb half[64][72]; sc f32[64][68]. 41984 B
// ============================================================================
#define H_LDH 40
#define PB_LD 72
#define SC_LD 68
#define AH_SMEM 41984

__global__ void __launch_bounds__(128, 5)
attn_heads()
{
    extern __shared__ char smc[];
    __half* qs = (__half*)smc;
    __half* ks = (__half*)(smc + 5120);
    __half* vs = (__half*)(smc + 10240);
    __half* pb = (__half*)(smc + 15360);
    float*  sc = (float*)(smc + 24576);

    const int tid  = threadIdx.x;
    const int wid  = tid >> 5;
    const int lane = tid & 31;
    const int win  = blockIdx.x;
    const int h    = blockIdx.y;
    const int gg = lane >> 2, tig = lane & 3;

    // load Q/K/V head slices + zero pads
    {
        const __half* base = g_qkvh + (size_t)win * 49 * 576 + h * 32;
        for (int idx = tid; idx < 3 * 49 * 4; idx += 128) {
            int m = idx / 196, rem = idx - m * 196;
            int r = rem >> 2, c8 = rem & 3;
            float4 v = *(const float4*)(base + (size_t)r * 576 + m * 192 + c8 * 8);
            __half* dst = (m == 0 ? qs : (m == 1 ? ks : vs));
            *(float4*)(dst + r * H_LDH + c8 * 8) = v;
        }
        float4 z = make_float4(0.f, 0.f, 0.f, 0.f);
        for (int idx = tid; idx < 3 * 15 * 4; idx += 128) {
            int m = idx / 60, rem = idx - m * 60;
            int r = 49 + (rem >> 2), c8 = rem & 3;
            __half* dst = (m == 0 ? qs : (m == 1 ? ks : vs));
            *(float4*)(dst + r * H_LDH + c8 * 8) = z;
        }
        for (int idx = tid; idx < 576; idx += 128)
            *(float4*)(pb + idx * 8) = z;
    }
    __syncthreads();

    // ---- scores = Q @ K^T : mma.sync, rt = wid ----
    {
        // A: Q rows wid*16+(lane&15), col (lane>>4)*8 ; two k16 steps
        const uint32_t qa = smem_u32(qs) +
            (((wid * 16 + (lane & 15)) * H_LDH + ((lane >> 4) << 3)) << 1);
        uint32_t RA[2][4];
        ldsm_x4(RA[0], qa);
        ldsm_x4(RA[1], qa + 32);
        // B: K stored [n][k]: non-trans ldsm; per-lane row/col offsets
        const uint32_t krow = (lane & 7) + ((lane >> 4) << 3);
        const uint32_t kcol = ((lane >> 3) & 1) << 3;
        const uint32_t kbase = smem_u32(ks) + ((krow * H_LDH + kcol) << 1);
#pragma unroll
        for (int ct = 0; ct < 4; ct++) {
            uint32_t RB0[4], RB1[4];
            ldsm_x4(RB0, kbase + ((ct * 16 * H_LDH) << 1));
            ldsm_x4(RB1, kbase + ((ct * 16 * H_LDH) << 1) + 32);
            float c0[4] = {0.f, 0.f, 0.f, 0.f}, c1[4] = {0.f, 0.f, 0.f, 0.f};
            mma_h(c0, RA[0], RB0[0], RB0[1]);
            mma_h(c0, RA[1], RB1[0], RB1[1]);
            mma_h(c1, RA[0], RB0[2], RB0[3]);
            mma_h(c1, RA[1], RB1[2], RB1[3]);
            int row = wid * 16 + gg;
            int col = ct * 16 + tig * 2;
            *(float2*)(sc + row * SC_LD + col)           = make_float2(c0[0], c0[1]);
            *(float2*)(sc + (row + 8) * SC_LD + col)     = make_float2(c0[2], c0[3]);
            *(float2*)(sc + row * SC_LD + col + 8)       = make_float2(c1[0], c1[1]);
            *(float2*)(sc + (row + 8) * SC_LD + col + 8) = make_float2(c1[2], c1[3]);
        }
    }
    __syncthreads();

    // ---- softmax (+ bias) fp32, probs -> fp16 pb (unchanged) ----
    {
        const float* bh = g_bias + h * 2401;
        for (int r = wid; r < 49; r += 4) {
            float* srow = sc + r * SC_LD;
            int j0 = lane, j1 = lane + 32;
            float v0 = srow[j0] + bh[r * 49 + j0];
            float v1 = (j1 < 49) ? srow[j1] + bh[r * 49 + j1] : -1e30f;
            float m = fmaxf(v0, v1);
#pragma unroll
            for (int o = 16; o; o >>= 1) m = fmaxf(m, __shfl_xor_sync(~0u, m, o));
            float e0 = expf(v0 - m);
            float e1 = (j1 < 49) ? expf(v1 - m) : 0.f;
            float s = e0 + e1;
#pragma unroll
            for (int o = 16; o; o >>= 1) s += __shfl_xor_sync(~0u, s, o);
            float inv = 1.f / s;
            __half* prow = pb + r * PB_LD;
            prow[j0] = __float2half_rn(e0 * inv);
            if (j1 < 49) prow[j1] = __float2half_rn(e1 * inv);
        }
    }
    __syncthreads();

    // ---- PV : mma.sync; A = P (ldsm), B = V (ldsm trans) ----
    {
        const uint32_t pa = smem_u32(pb) +
            (((wid * 16 + (lane & 15)) * PB_LD + ((lane >> 4) << 3)) << 1);
        const uint32_t vrow = (lane & 7) + (((lane >> 3) & 1) << 3);
        const uint32_t vcol = (lane >> 4) << 3;
        const uint32_t vbase = smem_u32(vs) + ((vrow * H_LDH + vcol) << 1);
        float c[2][2][4];
#pragma unroll
        for (int ct = 0; ct < 2; ct++)
#pragma unroll
            for (int p = 0; p < 2; p++)
#pragma unroll
                for (int q = 0; q < 4; q++) c[ct][p][q] = 0.f;

#pragma unroll
        for (int k = 0; k < 4; k++) {
            uint32_t RA4[4];
            ldsm_x4(RA4, pa + k * 32);
#pragma unroll
            for (int ct = 0; ct < 2; ct++) {
                uint32_t RB[4];
                ldsm_x4_t(RB, vbase + (((k * 16) * H_LDH + ct * 16) << 1));
                mma_h(c[ct][0], RA4, RB[0], RB[1]);
                mma_h(c[ct][1], RA4, RB[2], RB[3]);
            }
        }
        // store PV out to sc (fp32), same layout as before
#pragma unroll
        for (int ct = 0; ct < 2; ct++)
#pragma unroll
            for (int p = 0; p < 2; p++) {
                int row = wid * 16 + gg;
                int col = ct * 16 + p * 8 + tig * 2;
                *(float2*)(sc + row * SC_LD + col)       = make_float2(c[ct][p][0], c[ct][p][1]);
                *(float2*)(sc + (row + 8) * SC_LD + col) = make_float2(c[ct][p][2], c[ct][p][3]);
            }
    }
    __syncthreads();

    // ---- attn-out rows 0..48 -> fp16 g_attnh ----
    {
        __half* base = g_attnh + (size_t)win * 49 * DIMC + h * 32;
        for (int idx = tid; idx < 49 * 16; idx += 128) {
            int r = idx >> 4, c2 = idx & 15;
            __half2 h2 = __floats2half2_rn(sc[r * SC_LD + c2 * 2], sc[r * SC_LD + c2 * 2 + 1]);
            *(__half2*)(base + (size_t)r * DIMC + c2 * 2) = h2;
        }
    }
}

// ============================================================================
// Kernel C (FUSED): proj + residual + LN2 + MLP + out (round-15 structure,
// hoisted ldsm base addresses).
// ============================================================================
#define PJ_LD 196
#define MD_LD 196
#define AS_LD 200
#define TAIL_SMEM 101376

__global__ void __launch_bounds__(256, 2)
tail_kernel(const float* __restrict__ x,
            const float* __restrict__ projb,
            const float* __restrict__ ln2w, const float* __restrict__ ln2b,
            const float* __restrict__ fc1b, const float* __restrict__ fc2b,
            float* __restrict__ out)
{
    extern __shared__ char smc[];
    __half* xh   = (__half*)smc;
    float*  st   = (float*)(smc + 25600);
    bf16*   as   = (bf16*)(smc + 75776);
    float*  mid  = (float*)(smc + 25600);   // overlays st (after LN2)
    bf16*   midb = (bf16*)smc;              // overlays xh (after proj GEMM)

    const int tid  = threadIdx.x;
    const int wid  = tid >> 5;
    const int lane = tid & 31;
    const int t0   = blockIdx.x * 64;
    const int rtg  = wid & 1;
    const int ctg  = wid >> 1;
    const int gg = lane >> 2, tig = lane & 3;

    // hoisted per-thread A-row/col offsets (element units)
    const int aoff_row = rtg * 32 + (lane & 15);
    const int aoff_col = (lane >> 4) << 3;

    // ---- load attn-out (fp16, coalesced) ----
    {
        const float4* src = (const float4*)(g_attnh + (size_t)t0 * DIMC);
        for (int idx = tid; idx < 64 * 24; idx += 256) {
            int r = idx / 24, c8 = idx - r * 24;
            *(float4*)(xh + r * XH_LD + c8 * 8) = src[idx];
        }
    }
    __syncthreads();

    // ---- proj GEMM fp16 mma.sync -> st ----
    {
        const uint32_t abase = smem_u32(xh) + ((aoff_row * XH_LD + aoff_col) << 1);
        const uint32_t arow16 = (16 * XH_LD) << 1;

        float acc[2][3][2][4];
#pragma unroll
        for (int i = 0; i < 2; i++)
#pragma unroll
            for (int j = 0; j < 3; j++)
#pragma unroll
                for (int p = 0; p < 2; p++)
#pragma unroll
                    for (int q = 0; q < 4; q++) acc[i][j][p][q] = 0.f;

        uint4 wb[3];
#pragma unroll
        for (int j = 0; j < 3; j++)
            wb[j] = g_projp[((size_t)(ctg * 3 + j) * 12) * 32 + lane];

        for (int k = 0; k < 12; k++) {
            uint4 nb[3];
            if (k < 11) {
#pragma unroll
                for (int j = 0; j < 3; j++)
                    nb[j] = g_projp[((size_t)(ctg * 3 + j) * 12 + k + 1) * 32 + lane];
            }
            uint32_t RA[2][4];
#pragma unroll
            for (int i = 0; i < 2; i++)
                ldsm_x4(RA[i], abase + i * arow16 + k * 32);
#pragma unroll
            for (int j = 0; j < 3; j++)
#pragma unroll
                for (int i = 0; i < 2; i++) {
                    mma_h(acc[i][j][0], RA[i], wb[j].x, wb[j].y);
                    mma_h(acc[i][j][1], RA[i], wb[j].z, wb[j].w);
                }
            if (k < 11) { wb[0] = nb[0]; wb[1] = nb[1]; wb[2] = nb[2]; }
        }
#pragma unroll
        for (int i = 0; i < 2; i++)
#pragma unroll
            for (int j = 0; j < 3; j++)
#pragma unroll
                for (int p = 0; p < 2; p++) {
                    int col = (ctg * 3 + j) * 16 + p * 8 + tig * 2;
                    int row = rtg * 32 + i * 16 + gg;
                    *(float2*)(st + row * PJ_LD + col)       = make_float2(acc[i][j][p][0], acc[i][j][p][1]);
                    *(float2*)(st + (row + 8) * PJ_LD + col) = make_float2(acc[i][j][p][2], acc[i][j][p][3]);
                }
    }
    __syncthreads();

    // ---- residual: st += x + projb ----
    {
        const int r = tid & 63;
        const int t = t0 + r;
        const int win = t / 49, pos = t - win * 49;
        const int b = win >> 10, wh = (win >> 5) & 31, ww = win & 31;
        const int pi = pos / 7;
        const float* src = x + (size_t)b * DIMC * HWSQ + (wh * 7 + pi) * HWI + (ww * 7 + pos - pi * 7);
        for (int c = tid >> 6; c < DIMC; c += 4)
            st[r * PJ_LD + c] += src[(size_t)c * HWSQ] + projb[c];
    }
    __syncthreads();

    // ---- LN2: h1 -> g_h1, h1n -> as (smem bf16) ----
    for (int r = wid; r < 64; r += 8) {
        float v[6]; float s = 0.f;
#pragma unroll
        for (int q = 0; q < 6; q++) { v[q] = st[r * PJ_LD + lane + q * 32]; s += v[q]; }
#pragma unroll
        for (int o = 16; o; o >>= 1) s += __shfl_xor_sync(~0u, s, o);
        float mu = s * (1.f / 192.f);
        float vs = 0.f;
#pragma unroll
        for (int q = 0; q < 6; q++) { float d = v[q] - mu; vs += d * d; }
#pragma unroll
        for (int o = 16; o; o >>= 1) vs += __shfl_xor_sync(~0u, vs, o);
        float rs = rsqrtf(vs * (1.f / 192.f) + 1e-5f);
        size_t base = (size_t)(t0 + r) * DIMC;
#pragma unroll
        for (int q = 0; q < 6; q++) {
            int c = lane + q * 32;
            g_h1[base + c] = v[q];
            as[r * AS_LD + c] = __float2bfloat16((v[q] - mu) * rs * ln2w[c] + ln2b[c]);
        }
    }
    __syncthreads();

    // ---- MLP: 4 K-chunks, GEMM2 register-resident ----
    const uint32_t asbase = smem_u32(as) + ((aoff_row * AS_LD + aoff_col) << 1);
    const uint32_t mbbase = smem_u32(midb) + ((aoff_row * AS_LD + aoff_col) << 1);
    const uint32_t asrow16 = (16 * AS_LD) << 1;

    float acc2[2][3][2][4];
#pragma unroll
    for (int i = 0; i < 2; i++)
#pragma unroll
        for (int j = 0; j < 3; j++)
#pragma unroll
            for (int p = 0; p < 2; p++)
#pragma unroll
                for (int q = 0; q < 4; q++) acc2[i][j][p][q] = 0.f;

    for (int chunk = 0; chunk < 4; chunk++) {
        // GEMM1 bf16 mma.sync -> mid
        {
            float acc[2][3][2][4];
#pragma unroll
            for (int i = 0; i < 2; i++)
#pragma unroll
                for (int j = 0; j < 3; j++)
#pragma unroll
                    for (int p = 0; p < 2; p++)
#pragma unroll
                        for (int q = 0; q < 4; q++) acc[i][j][p][q] = 0.f;

            for (int k = 0; k < 12; k++) {
                uint4 wb[3];
#pragma unroll
                for (int j = 0; j < 3; j++)
                    wb[j] = g_fc1p[((size_t)(chunk * 12 + ctg * 3 + j) * 12 + k) * 32 + lane];
                uint32_t RA[2][4];
#pragma unroll
                for (int i = 0; i < 2; i++)
                    ldsm_x4(RA[i], asbase + i * asrow16 + k * 32);
#pragma unroll
                for (int j = 0; j < 3; j++)
#pragma unroll
                    for (int i = 0; i < 2; i++) {
                        mma_b(acc[i][j][0], RA[i], wb[j].x, wb[j].y);
                        mma_b(acc[i][j][1], RA[i], wb[j].z, wb[j].w);
                    }
            }
#pragma unroll
            for (int i = 0; i < 2; i++)
#pragma unroll
                for (int j = 0; j < 3; j++)
#pragma unroll
                    for (int p = 0; p < 2; p++) {
                        int col = (ctg * 3 + j) * 16 + p * 8 + tig * 2;
                        int row = rtg * 32 + i * 16 + gg;
                        *(float2*)(mid + row * MD_LD + col)       = make_float2(acc[i][j][p][0], acc[i][j][p][1]);
                        *(float2*)(mid + (row + 8) * MD_LD + col) = make_float2(acc[i][j][p][2], acc[i][j][p][3]);
                    }
        }
        __syncthreads();

        // bias + exact GELU -> midb bf16 (vectorized x4)
        for (int idx = tid; idx < 64 * 48; idx += 256) {
            int r = idx / 48, c4 = (idx - r * 48) * 4;
            float4 m  = *(const float4*)(mid + r * MD_LD + c4);
            float4 bb = *(const float4*)(fc1b + chunk * 192 + c4);
            float v0 = m.x + bb.x, v1 = m.y + bb.y, v2 = m.z + bb.z, v3 = m.w + bb.w;
            float g0 = 0.5f * v0 * (1.f + erff(v0 * 0.70710678118654752f));
            float g1 = 0.5f * v1 * (1.f + erff(v1 * 0.70710678118654752f));
            float g2 = 0.5f * v2 * (1.f + erff(v2 * 0.70710678118654752f));
            float g3 = 0.5f * v3 * (1.f + erff(v3 * 0.70710678118654752f));
            __nv_bfloat162 b0 = __floats2bfloat162_rn(g0, g1);
            __nv_bfloat162 b1 = __floats2bfloat162_rn(g2, g3);
            uint2 u; u.x = *(uint32_t*)&b0; u.y = *(uint32_t*)&b1;
            *(uint2*)(midb + r * AS_LD + c4) = u;
        }
        __syncthreads();

        // GEMM2 partial bf16 mma.sync (B double-buffered), acc2 persistent
        {
            uint4 wb[3];
#pragma unroll
            for (int j = 0; j < 3; j++)
                wb[j] = g_fc2p[((size_t)(ctg * 3 + j) * 48 + chunk * 12) * 32 + lane];
            for (int k = 0; k < 12; k++) {
                uint4 nb[3];
                if (k < 11) {
#pragma unroll
                    for (int j = 0; j < 3; j++)
                        nb[j] = g_fc2p[((size_t)(ctg * 3 + j) * 48 + chunk * 12 + k + 1) * 32 + lane];
                }
                uint32_t RA[2][4];
#pragma unroll
                for (int i = 0; i < 2; i++)
                    ldsm_x4(RA[i], mbbase + i * asrow16 + k * 32);
#pragma unroll
                for (int j = 0; j < 3; j++)
#pragma unroll
                    for (int i = 0; i < 2; i++) {
                        mma_b(acc2[i][j][0], RA[i], wb[j].x, wb[j].y);
                        mma_b(acc2[i][j][1], RA[i], wb[j].z, wb[j].w);
                    }
                if (k < 11) { wb[0] = nb[0]; wb[1] = nb[1]; wb[2] = nb[2]; }
            }
        }
        __syncthreads();
    }

    // ---- store MLP output -> mid ----
#pragma unroll
    for (int i = 0; i < 2; i++)
#pragma unroll
        for (int j = 0; j < 3; j++)
#pragma unroll
            for (int p = 0; p < 2; p++) {
                int col = (ctg * 3 + j) * 16 + p * 8 + tig * 2;
                int row = rtg * 32 + i * 16 + gg;
                *(float2*)(mid + row * MD_LD + col)       = make_float2(acc2[i][j][p][0], acc2[i][j][p][1]);
                *(float2*)(mid + (row + 8) * MD_LD + col) = make_float2(acc2[i][j][p][2], acc2[i][j][p][3]);
            }
    __syncthreads();

    // ---- final pass 1 (c-fast, coalesced g_h1 reads): mid = (mid+h1)+fc2b ----
    for (int idx = tid; idx < 64 * 48; idx += 256) {
        int r = idx / 48, c4 = (idx - r * 48) * 4;
        float4 m  = *(const float4*)(mid + r * MD_LD + c4);
        float4 h  = *(const float4*)(g_h1 + (size_t)(t0 + r) * DIMC + c4);
        float4 bb = *(const float4*)(fc2b + c4);
        m.x = (m.x + h.x) + bb.x;
        m.y = (m.y + h.y) + bb.y;
        m.z = (m.z + h.z) + bb.z;
        m.w = (m.w + h.w) + bb.w;
        *(float4*)(mid + r * MD_LD + c4) = m;
    }
    __syncthreads();

    // ---- final pass 2 (r-fast): coalesced NCHW scatter ----
    for (int idx = tid; idx < 64 * 192; idx += 256) {
        int r = idx & 63;
        int c = idx >> 6;
        int t = t0 + r;
        int win = t / 49; int pos = t - win * 49;
        int b  = win >> 10;
        int wh = (win >> 5) & 31;
        int ww = win & 31;
        int pi = pos / 7;
        int hh = wh * 7 + pi;
        int wx = ww * 7 + (pos - pi * 7);
        out[((size_t)(b * DIMC + c)) * HWSQ + hh * HWI + wx] = mid[r * MD_LD + c];
    }
}

// ============================================================================
extern "C" void kernel_launch(void* const* d_in, const int* in_sizes, int n_in,
                              void* d_out, int out_size)
{
    (void)in_sizes; (void)n_in; (void)out_size;
    const float* x     = (const float*)d_in[0];
    const float* ln1w  = (const float*)d_in[1];
    const float* ln1b  = (const float*)d_in[2];
    const float* qkvw  = (const float*)d_in[3];
    const float* qkvb  = (const float*)d_in[4];
    const float* projw = (const float*)d_in[5];
    const float* projb = (const float*)d_in[6];
    const float* rpb   = (const float*)d_in[7];
    const float* ln2w  = (const float*)d_in[8];
    const float* ln2b  = (const float*)d_in[9];
    const float* fc1w  = (const float*)d_in[10];
    const float* fc1b  = (const float*)d_in[11];
    const float* fc2w  = (const float*)d_in[12];
    const float* fc2b  = (const float*)d_in[13];
    const int*   ridx  = (const int*)  d_in[14];
    float* out = (float*)d_out;

    cudaFuncSetAttribute(qkv_gemm,    cudaFuncAttributeMaxDynamicSharedMemorySize, QKV_SMEM);
    cudaFuncSetAttribute(attn_heads,  cudaFuncAttributeMaxDynamicSharedMemorySize, AH_SMEM);
    cudaFuncSetAttribute(tail_kernel, cudaFuncAttributeMaxDynamicSharedMemorySize, TAIL_SMEM);

    prelude<<<(PRE_TOT + 511) / 512, 512>>>(qkvw, projw, fc1w, fc2w, rpb, ridx);

    qkv_gemm<<<TTOK / 64, 256, QKV_SMEM>>>(x, ln1w, ln1b, qkvb);

    dim3 ag(NWIN, 6);
    attn_heads<<<ag, 128, AH_SMEM>>>();

    tail_kernel<<<TTOK / 64, 256, TAIL_SMEM>>>(x, projb, ln2w, ln2b, fc1b, fc2b, out);
}

// round 17
// speedup vs baseline: 1.0680x; 1.0680x over previous
#include <cuda_runtime.h>
#include <cuda_bf16.h>
#include <cuda_fp16.h>
#include <cmath>
#include <cstdint>

typedef __nv_bfloat16 bf16;

// ---------------- problem constants ----------------
#define NWIN   8192
#define TTOK   401408
#define HWI    224
#define HWSQ   50176
#define DIMC   192

// scratch (allocation-free static device arrays)
__device__ __half g_qkvh [(size_t)TTOK * 576];   // QKV (scaled/biased, fp16)
__device__ __half g_attnh[(size_t)TTOK * DIMC];  // attention out (fp16)
__device__ float  g_h1  [(size_t)TTOK * DIMC];   // x + attn branch (fp32)
__device__ float  g_bias [6 * 49 * 49];

// pre-packed B fragments (mma.sync m16n8k16 layout), one uint4 per lane per 16x16 tile
#define N_QKVP  (36 * 12 * 32)
#define N_PROJP (12 * 12 * 32)
#define N_FC1P  (48 * 12 * 32)
#define N_FC2P  (12 * 48 * 32)
__device__ uint4 g_qkvp [N_QKVP];
__device__ uint4 g_projp[N_PROJP];
__device__ uint4 g_fc1p [N_FC1P];
__device__ uint4 g_fc2p [N_FC2P];

// ---------------- mma.sync helpers ----------------
__device__ __forceinline__ uint32_t smem_u32(const void* p) {
    uint32_t a;
    asm("{ .reg .u64 t; cvta.to.shared.u64 t, %1; cvt.u32.u64 %0, t; }" : "=r"(a) : "l"(p));
    return a;
}
__device__ __forceinline__ void ldsm_x4(uint32_t (&r)[4], uint32_t addr) {
    asm volatile("ldmatrix.sync.aligned.m8n8.x4.shared.b16 {%0,%1,%2,%3}, [%4];"
        : "=r"(r[0]), "=r"(r[1]), "=r"(r[2]), "=r"(r[3]) : "r"(addr));
}
__device__ __forceinline__ void ldsm_x4_t(uint32_t (&r)[4], uint32_t addr) {
    asm volatile("ldmatrix.sync.aligned.m8n8.x4.trans.shared.b16 {%0,%1,%2,%3}, [%4];"
        : "=r"(r[0]), "=r"(r[1]), "=r"(r[2]), "=r"(r[3]) : "r"(addr));
}
__device__ __forceinline__ void mma_h(float (&c)[4], const uint32_t (&a)[4], uint32_t b0, uint32_t b1) {
    asm volatile("mma.sync.aligned.m16n8k16.row.col.f32.f16.f16.f32 "
        "{%0,%1,%2,%3},{%4,%5,%6,%7},{%8,%9},{%0,%1,%2,%3};"
        : "+f"(c[0]), "+f"(c[1]), "+f"(c[2]), "+f"(c[3])
        : "r"(a[0]), "r"(a[1]), "r"(a[2]), "r"(a[3]), "r"(b0), "r"(b1));
}
__device__ __forceinline__ void mma_b(float (&c)[4], const uint32_t (&a)[4], uint32_t b0, uint32_t b1) {
    asm volatile("mma.sync.aligned.m16n8k16.row.col.f32.bf16.bf16.f32 "
        "{%0,%1,%2,%3},{%4,%5,%6,%7},{%8,%9},{%0,%1,%2,%3};"
        : "+f"(c[0]), "+f"(c[1]), "+f"(c[2]), "+f"(c[3])
        : "r"(a[0]), "r"(a[1]), "r"(a[2]), "r"(a[3]), "r"(b0), "r"(b1));
}

__device__ __forceinline__ uint32_t pack_h2(float x, float y) {
    __half2 h = __floats2half2_rn(x, y); return *(uint32_t*)&h;
}
__device__ __forceinline__ uint32_t pack_b2(float x, float y) {
    __nv_bfloat162 h = __floats2bfloat162_rn(x, y); return *(uint32_t*)&h;
}
__device__ __forceinline__ uint4 pack_tile_h(const float* W, int N, int K0, int N0, int lane) {
    int g = lane >> 2, tig = lane & 3;
    int k0 = K0 + tig * 2;
    uint4 u;
    u.x = pack_h2(W[(size_t)k0 * N + N0 + g],       W[(size_t)(k0 + 1) * N + N0 + g]);
    u.y = pack_h2(W[(size_t)(k0 + 8) * N + N0 + g], W[(size_t)(k0 + 9) * N + N0 + g]);
    u.z = pack_h2(W[(size_t)k0 * N + N0 + 8 + g],       W[(size_t)(k0 + 1) * N + N0 + 8 + g]);
    u.w = pack_h2(W[(size_t)(k0 + 8) * N + N0 + 8 + g], W[(size_t)(k0 + 9) * N + N0 + 8 + g]);
    return u;
}
__device__ __forceinline__ uint4 pack_tile_b(const float* W, int N, int K0, int N0, int lane) {
    int g = lane >> 2, tig = lane & 3;
    int k0 = K0 + tig * 2;
    uint4 u;
    u.x = pack_b2(W[(size_t)k0 * N + N0 + g],       W[(size_t)(k0 + 1) * N + N0 + g]);
    u.y = pack_b2(W[(size_t)(k0 + 8) * N + N0 + g], W[(size_t)(k0 + 9) * N + N0 + g]);
    u.z = pack_b2(W[(size_t)k0 * N + N0 + 8 + g],       W[(size_t)(k0 + 1) * N + N0 + 8 + g]);
    u.w = pack_b2(W[(size_t)(k0 + 8) * N + N0 + 8 + g], W[(size_t)(k0 + 9) * N + N0 + 8 + g]);
    return u;
}

// ---------------- prelude: pack weights + bias table ----------------
#define N_BIAS 14406
#define PRE_TOT (N_QKVP + N_PROJP + N_FC1P + N_FC2P + N_BIAS)

__global__ void prelude(const float* __restrict__ qkvw, const float* __restrict__ projw,
                        const float* __restrict__ fc1w, const float* __restrict__ fc2w,
                        const float* __restrict__ rpb,  const int* __restrict__ relidx)
{
    int i = blockIdx.x * blockDim.x + threadIdx.x;
    if (i < N_QKVP) {
        int lane = i & 31, t = i >> 5, T = t / 12, K = t - T * 12;
        g_qkvp[i] = pack_tile_h(qkvw, 576, K * 16, T * 16, lane); return;
    }
    i -= N_QKVP;
    if (i < N_PROJP) {
        int lane = i & 31, t = i >> 5, T = t / 12, K = t - T * 12;
        g_projp[i] = pack_tile_h(projw, 192, K * 16, T * 16, lane); return;
    }
    i -= N_PROJP;
    if (i < N_FC1P) {
        int lane = i & 31, t = i >> 5, T = t / 12, K = t - T * 12;
        g_fc1p[i] = pack_tile_b(fc1w, 768, K * 16, T * 16, lane); return;
    }
    i -= N_FC1P;
    if (i < N_FC2P) {
        int lane = i & 31, t = i >> 5, T = t / 48, K = t - T * 48;
        g_fc2p[i] = pack_tile_b(fc2w, 192, K * 16, T * 16, lane); return;
    }
    i -= N_FC2P;
    if (i < N_BIAS) {
        int h = i / 2401, rj = i - h * 2401;
        g_bias[i] = rpb[relidx[rj] * 6 + h];
    }
}

// ============================================================================
// Kernel A: batched QKV GEMM, fp16 mma.sync; in-register epilogue to half
// staging, then one coalesced uint4 copy to g_qkvh.
// smem: xnf f32[64][196]@0 (st_h half[64][200] overlays); xh half[64][200]@50176
// ============================================================================
#define XN_LD 196
#define XH_LD 200
#define STH_LD 200
#define QKV_SMEM 75776

__global__ void __launch_bounds__(256, 2)
qkv_gemm(const float* __restrict__ x,
         const float* __restrict__ ln1w, const float* __restrict__ ln1b,
         const float* __restrict__ qkvb)
{
    extern __shared__ char smc[];
    float*  xnf  = (float*)smc;
    __half* st_h = (__half*)smc;               // overlay (used after LN1)
    __half* xh   = (__half*)(smc + 50176);

    const int tid  = threadIdx.x;
    const int wid  = tid >> 5;
    const int lane = tid & 31;
    const int t0   = blockIdx.x * 64;

    // gather x (fp32)
    {
        const int r = tid & 63;
        const int t = t0 + r;
        const int win = t / 49, pos = t - win * 49;
        const int b = win >> 10, wh = (win >> 5) & 31, ww = win & 31;
        const int pi = pos / 7;
        const float* src = x + (size_t)b * DIMC * HWSQ + (wh * 7 + pi) * HWI + (ww * 7 + pos - pi * 7);
        for (int c = tid >> 6; c < DIMC; c += 4)
            xnf[r * XN_LD + c] = src[(size_t)c * HWSQ];
    }
    __syncthreads();

    // LN1 (fp32 stats) -> fp16 A operand
    for (int r = wid; r < 64; r += 8) {
        float v[6]; float s = 0.f;
#pragma unroll
        for (int q = 0; q < 6; q++) { v[q] = xnf[r * XN_LD + lane + q * 32]; s += v[q]; }
#pragma unroll
        for (int o = 16; o; o >>= 1) s += __shfl_xor_sync(~0u, s, o);
        float mu = s * (1.f / 192.f);
        float vs = 0.f;
#pragma unroll
        for (int q = 0; q < 6; q++) { float d = v[q] - mu; vs += d * d; }
#pragma unroll
        for (int o = 16; o; o >>= 1) vs += __shfl_xor_sync(~0u, vs, o);
        float rs = rsqrtf(vs * (1.f / 192.f) + 1e-5f);
#pragma unroll
        for (int q = 0; q < 6; q++) {
            int c = lane + q * 32;
            xh[r * XH_LD + c] = __float2half_rn((v[q] - mu) * rs * ln1w[c] + ln1b[c]);
        }
    }
    __syncthreads();

    const int rtg = wid & 1;
    const int ctg = wid >> 1;
    const int gg = lane >> 2, tig = lane & 3;
    const float scale = 0.17677669529663687f;

    const uint32_t abase = smem_u32(xh) +
        (((rtg * 32 + (lane & 15)) * XH_LD + ((lane >> 4) << 3)) << 1);
    const uint32_t arow16 = (16 * XH_LD) << 1;

    for (int chunk = 0; chunk < 3; chunk++) {
        float acc[2][3][2][4];
#pragma unroll
        for (int i = 0; i < 2; i++)
#pragma unroll
            for (int j = 0; j < 3; j++)
#pragma unroll
                for (int p = 0; p < 2; p++)
#pragma unroll
                    for (int q = 0; q < 4; q++) acc[i][j][p][q] = 0.f;

        uint4 wb[3];
#pragma unroll
        for (int j = 0; j < 3; j++)
            wb[j] = g_qkvp[((size_t)(chunk * 12 + ctg * 3 + j) * 12) * 32 + lane];

        for (int k = 0; k < 12; k++) {
            uint4 nb[3];
            if (k < 11) {
#pragma unroll
                for (int j = 0; j < 3; j++)
                    nb[j] = g_qkvp[((size_t)(chunk * 12 + ctg * 3 + j) * 12 + k + 1) * 32 + lane];
            }
            uint32_t RA[2][4];
#pragma unroll
            for (int i = 0; i < 2; i++)
                ldsm_x4(RA[i], abase + i * arow16 + k * 32);
#pragma unroll
            for (int j = 0; j < 3; j++)
#pragma unroll
                for (int i = 0; i < 2; i++) {
                    mma_h(acc[i][j][0], RA[i], wb[j].x, wb[j].y);
                    mma_h(acc[i][j][1], RA[i], wb[j].z, wb[j].w);
                }
            if (k < 11) { wb[0] = nb[0]; wb[1] = nb[1]; wb[2] = nb[2]; }
        }

        // in-register epilogue: bias + q-scale + fp16 pack -> st_h
        {
            const float sc = (chunk == 0) ? scale : 1.f;
#pragma unroll
            for (int j = 0; j < 3; j++)
#pragma unroll
                for (int p = 0; p < 2; p++) {
                    int col = (ctg * 3 + j) * 16 + p * 8 + tig * 2;
                    float b0 = qkvb[chunk * 192 + col];
                    float b1 = qkvb[chunk * 192 + col + 1];
#pragma unroll
                    for (int i = 0; i < 2; i++) {
                        int row = rtg * 32 + i * 16 + gg;
                        *(uint32_t*)(st_h + row * STH_LD + col) =
                            pack_h2((acc[i][j][p][0] + b0) * sc, (acc[i][j][p][1] + b1) * sc);
                        *(uint32_t*)(st_h + (row + 8) * STH_LD + col) =
                            pack_h2((acc[i][j][p][2] + b0) * sc, (acc[i][j][p][3] + b1) * sc);
                    }
                }
        }
        __syncthreads();

        // coalesced copy st_h -> g_qkvh
        for (int idx = tid; idx < 64 * 24; idx += 256) {
            int r = idx / 24, c8 = (idx - r * 24) * 8;
            *(uint4*)(g_qkvh + (size_t)(t0 + r) * 576 + chunk * 192 + c8) =
                *(const uint4*)(st_h + r * STH_LD + c8);
        }
        __syncthreads();
    }
}

// ============================================================================
// Kernel B: per window-head attention, fp16 mma.sync; PV written straight
// from registers to g_attnh (row<49 predicated).
// smem: qs/ks/vs half[64][40]; pb half[64][72]; sc f32[64][68]. 41984 B
// ============================================================================
#define H_LDH 40
#define PB_LD 72
#define SC_LD 68
#define AH_SMEM 41984

__global__ void __launch_bounds__(128, 5)
attn_heads()
{
    extern __shared__ char smc[];
    __half* qs = (__half*)smc;
    __half* ks = (__half*)(smc + 5120);
    __half* vs = (__half*)(smc + 10240);
    __half* pb = (__half*)(smc + 15360);
    float*  sc = (float*)(smc + 24576);

    const int tid  = threadIdx.x;
    const int wid  = tid >> 5;
    const int lane = tid & 31;
    const int win  = blockIdx.x;
    const int h    = blockIdx.y;
    const int gg = lane >> 2, tig = lane & 3;

    // load Q/K/V head slices + zero pads
    {
        const __half* base = g_qkvh + (size_t)win * 49 * 576 + h * 32;
        for (int idx = tid; idx < 3 * 49 * 4; idx += 128) {
            int m = idx / 196, rem = idx - m * 196;
            int r = rem >> 2, c8 = rem & 3;
            float4 v = *(const float4*)(base + (size_t)r * 576 + m * 192 + c8 * 8);
            __half* dst = (m == 0 ? qs : (m == 1 ? ks : vs));
            *(float4*)(dst + r * H_LDH + c8 * 8) = v;
        }
        float4 z = make_float4(0.f, 0.f, 0.f, 0.f);
        for (int idx = tid; idx < 3 * 15 * 4; idx += 128) {
            int m = idx / 60, rem = idx - m * 60;
            int r = 49 + (rem >> 2), c8 = rem & 3;
            __half* dst = (m == 0 ? qs : (m == 1 ? ks : vs));
            *(float4*)(dst + r * H_LDH + c8 * 8) = z;
        }
        for (int idx = tid; idx < 576; idx += 128)
            *(float4*)(pb + idx * 8) = z;
    }
    __syncthreads();

    // ---- scores = Q @ K^T ----
    {
        const uint32_t qa = smem_u32(qs) +
            (((wid * 16 + (lane & 15)) * H_LDH + ((lane >> 4) << 3)) << 1);
        uint32_t RA[2][4];
        ldsm_x4(RA[0], qa);
        ldsm_x4(RA[1], qa + 32);
        const uint32_t krow = (lane & 7) + ((lane >> 4) << 3);
        const uint32_t kcol = ((lane >> 3) & 1) << 3;
        const uint32_t kbase = smem_u32(ks) + ((krow * H_LDH + kcol) << 1);
#pragma unroll
        for (int ct = 0; ct < 4; ct++) {
            uint32_t RB0[4], RB1[4];
            ldsm_x4(RB0, kbase + ((ct * 16 * H_LDH) << 1));
            ldsm_x4(RB1, kbase + ((ct * 16 * H_LDH) << 1) + 32);
            float c0[4] = {0.f, 0.f, 0.f, 0.f}, c1[4] = {0.f, 0.f, 0.f, 0.f};
            mma_h(c0, RA[0], RB0[0], RB0[1]);
            mma_h(c0, RA[1], RB1[0], RB1[1]);
            mma_h(c1, RA[0], RB0[2], RB0[3]);
            mma_h(c1, RA[1], RB1[2], RB1[3]);
            int row = wid * 16 + gg;
            int col = ct * 16 + tig * 2;
            *(float2*)(sc + row * SC_LD + col)           = make_float2(c0[0], c0[1]);
            *(float2*)(sc + (row + 8) * SC_LD + col)     = make_float2(c0[2], c0[3]);
            *(float2*)(sc + row * SC_LD + col + 8)       = make_float2(c1[0], c1[1]);
            *(float2*)(sc + (row + 8) * SC_LD + col + 8) = make_float2(c1[2], c1[3]);
        }
    }
    __syncthreads();

    // ---- softmax (+ bias) fp32, probs -> fp16 pb ----
    {
        const float* bh = g_bias + h * 2401;
        for (int r = wid; r < 49; r += 4) {
            float* srow = sc + r * SC_LD;
            int j0 = lane, j1 = lane + 32;
            float v0 = srow[j0] + bh[r * 49 + j0];
            float v1 = (j1 < 49) ? srow[j1] + bh[r * 49 + j1] : -1e30f;
            float m = fmaxf(v0, v1);
#pragma unroll
            for (int o = 16; o; o >>= 1) m = fmaxf(m, __shfl_xor_sync(~0u, m, o));
            float e0 = expf(v0 - m);
            float e1 = (j1 < 49) ? expf(v1 - m) : 0.f;
            float s = e0 + e1;
#pragma unroll
            for (int o = 16; o; o >>= 1) s += __shfl_xor_sync(~0u, s, o);
            float inv = 1.f / s;
            __half* prow = pb + r * PB_LD;
            prow[j0] = __float2half_rn(e0 * inv);
            if (j1 < 49) prow[j1] = __float2half_rn(e1 * inv);
        }
    }
    __syncthreads();

    // ---- PV: A = P (ldsm), B = V (ldsm trans); direct fp16 store ----
    {
        const uint32_t pa = smem_u32(pb) +
            (((wid * 16 + (lane & 15)) * PB_LD + ((lane >> 4) << 3)) << 1);
        const uint32_t vrow = (lane & 7) + (((lane >> 3) & 1) << 3);
        const uint32_t vcol = (lane >> 4) << 3;
        const uint32_t vbase = smem_u32(vs) + ((vrow * H_LDH + vcol) << 1);
        float c[2][2][4];
#pragma unroll
        for (int ct = 0; ct < 2; ct++)
#pragma unroll
            for (int p = 0; p < 2; p++)
#pragma unroll
                for (int q = 0; q < 4; q++) c[ct][p][q] = 0.f;

#pragma unroll
        for (int k = 0; k < 4; k++) {
            uint32_t RA4[4];
            ldsm_x4(RA4, pa + k * 32);
#pragma unroll
            for (int ct = 0; ct < 2; ct++) {
                uint32_t RB[4];
                ldsm_x4_t(RB, vbase + (((k * 16) * H_LDH + ct * 16) << 1));
                mma_h(c[ct][0], RA4, RB[0], RB[1]);
                mma_h(c[ct][1], RA4, RB[2], RB[3]);
            }
        }
        // direct store to g_attnh (rows < 49 only)
        __half* base = g_attnh + (size_t)win * 49 * DIMC + h * 32;
        const int row0 = wid * 16 + gg;
        const int row1 = row0 + 8;
#pragma unroll
        for (int ct = 0; ct < 2; ct++)
#pragma unroll
            for (int p = 0; p < 2; p++) {
                int col = ct * 16 + p * 8 + tig * 2;
                if (row0 < 49)
                    *(uint32_t*)(base + (size_t)row0 * DIMC + col) = pack_h2(c[ct][p][0], c[ct][p][1]);
                if (row1 < 49)
                    *(uint32_t*)(base + (size_t)row1 * DIMC + col) = pack_h2(c[ct][p][2], c[ct][p][3]);
            }
    }
}

// ============================================================================
// Kernel C (FUSED): proj + residual + LN2 + MLP + out; GEMM1 epilogue
// (bias+GELU+bf16) applied in-register.
// smem: xh@0 (25600, midb overlays); st@25600 (50176, mid overlays);
//       as@75776 (25600). 101376 B
// ============================================================================
#define PJ_LD 196
#define MD_LD 196
#define AS_LD 200
#define TAIL_SMEM 101376

__global__ void __launch_bounds__(256, 2)
tail_kernel(const float* __restrict__ x,
            const float* __restrict__ projb,
            const float* __restrict__ ln2w, const float* __restrict__ ln2b,
            const float* __restrict__ fc1b, const float* __restrict__ fc2b,
            float* __restrict__ out)
{
    extern __shared__ char smc[];
    __half* xh   = (__half*)smc;
    float*  st   = (float*)(smc + 25600);
    bf16*   as   = (bf16*)(smc + 75776);
    float*  mid  = (float*)(smc + 25600);   // overlays st (after LN2)
    bf16*   midb = (bf16*)smc;              // overlays xh (after proj GEMM)

    const int tid  = threadIdx.x;
    const int wid  = tid >> 5;
    const int lane = tid & 31;
    const int t0   = blockIdx.x * 64;
    const int rtg  = wid & 1;
    const int ctg  = wid >> 1;
    const int gg = lane >> 2, tig = lane & 3;

    const int aoff_row = rtg * 32 + (lane & 15);
    const int aoff_col = (lane >> 4) << 3;

    // ---- load attn-out (fp16, coalesced) ----
    {
        const float4* src = (const float4*)(g_attnh + (size_t)t0 * DIMC);
        for (int idx = tid; idx < 64 * 24; idx += 256) {
            int r = idx / 24, c8 = idx - r * 24;
            *(float4*)(xh + r * XH_LD + c8 * 8) = src[idx];
        }
    }
    __syncthreads();

    // ---- proj GEMM fp16 mma.sync -> st (fp32 staging needed for LN2) ----
    {
        const uint32_t abase = smem_u32(xh) + ((aoff_row * XH_LD + aoff_col) << 1);
        const uint32_t arow16 = (16 * XH_LD) << 1;

        float acc[2][3][2][4];
#pragma unroll
        for (int i = 0; i < 2; i++)
#pragma unroll
            for (int j = 0; j < 3; j++)
#pragma unroll
                for (int p = 0; p < 2; p++)
#pragma unroll
                    for (int q = 0; q < 4; q++) acc[i][j][p][q] = 0.f;

        uint4 wb[3];
#pragma unroll
        for (int j = 0; j < 3; j++)
            wb[j] = g_projp[((size_t)(ctg * 3 + j) * 12) * 32 + lane];

        for (int k = 0; k < 12; k++) {
            uint4 nb[3];
            if (k < 11) {
#pragma unroll
                for (int j = 0; j < 3; j++)
                    nb[j] = g_projp[((size_t)(ctg * 3 + j) * 12 + k + 1) * 32 + lane];
            }
            uint32_t RA[2][4];
#pragma unroll
            for (int i = 0; i < 2; i++)
                ldsm_x4(RA[i], abase + i * arow16 + k * 32);
#pragma unroll
            for (int j = 0; j < 3; j++)
#pragma unroll
                for (int i = 0; i < 2; i++) {
                    mma_h(acc[i][j][0], RA[i], wb[j].x, wb[j].y);
                    mma_h(acc[i][j][1], RA[i], wb[j].z, wb[j].w);
                }
            if (k < 11) { wb[0] = nb[0]; wb[1] = nb[1]; wb[2] = nb[2]; }
        }
#pragma unroll
        for (int i = 0; i < 2; i++)
#pragma unroll
            for (int j = 0; j < 3; j++)
#pragma unroll
                for (int p = 0; p < 2; p++) {
                    int col = (ctg * 3 + j) * 16 + p * 8 + tig * 2;
                    int row = rtg * 32 + i * 16 + gg;
                    *(float2*)(st + row * PJ_LD + col)       = make_float2(acc[i][j][p][0], acc[i][j][p][1]);
                    *(float2*)(st + (row + 8) * PJ_LD + col) = make_float2(acc[i][j][p][2], acc[i][j][p][3]);
                }
    }
    __syncthreads();

    // ---- residual: st += x + projb ----
    {
        const int r = tid & 63;
        const int t = t0 + r;
        const int win = t / 49, pos = t - win * 49;
        const int b = win >> 10, wh = (win >> 5) & 31, ww = win & 31;
        const int pi = pos / 7;
        const float* src = x + (size_t)b * DIMC * HWSQ + (wh * 7 + pi) * HWI + (ww * 7 + pos - pi * 7);
        for (int c = tid >> 6; c < DIMC; c += 4)
            st[r * PJ_LD + c] += src[(size_t)c * HWSQ] + projb[c];
    }
    __syncthreads();

    // ---- LN2: h1 -> g_h1, h1n -> as (smem bf16) ----
    for (int r = wid; r < 64; r += 8) {
        float v[6]; float s = 0.f;
#pragma unroll
        for (int q = 0; q < 6; q++) { v[q] = st[r * PJ_LD + lane + q * 32]; s += v[q]; }
#pragma unroll
        for (int o = 16; o; o >>= 1) s += __shfl_xor_sync(~0u, s, o);
        float mu = s * (1.f / 192.f);
        float vs = 0.f;
#pragma unroll
        for (int q = 0; q < 6; q++) { float d = v[q] - mu; vs += d * d; }
#pragma unroll
        for (int o = 16; o; o >>= 1) vs += __shfl_xor_sync(~0u, vs, o);
        float rs = rsqrtf(vs * (1.f / 192.f) + 1e-5f);
        size_t base = (size_t)(t0 + r) * DIMC;
#pragma unroll
        for (int q = 0; q < 6; q++) {
            int c = lane + q * 32;
            g_h1[base + c] = v[q];
            as[r * AS_LD + c] = __float2bfloat16((v[q] - mu) * rs * ln2w[c] + ln2b[c]);
        }
    }
    __syncthreads();

    // ---- MLP: 4 K-chunks, GEMM1 epilogue in-register, GEMM2 reg-resident ----
    const uint32_t asbase = smem_u32(as) + ((aoff_row * AS_LD + aoff_col) << 1);
    const uint32_t mbbase = smem_u32(midb) + ((aoff_row * AS_LD + aoff_col) << 1);
    const uint32_t asrow16 = (16 * AS_LD) << 1;

    float acc2[2][3][2][4];
#pragma unroll
    for (int i = 0; i < 2; i++)
#pragma unroll
        for (int j = 0; j < 3; j++)
#pragma unroll
            for (int p = 0; p < 2; p++)
#pragma unroll
                for (int q = 0; q < 4; q++) acc2[i][j][p][q] = 0.f;

    for (int chunk = 0; chunk < 4; chunk++) {
        // GEMM1 bf16 mma.sync; bias+GELU+pack applied in-register -> midb
        {
            float acc[2][3][2][4];
#pragma unroll
            for (int i = 0; i < 2; i++)
#pragma unroll
                for (int j = 0; j < 3; j++)
#pragma unroll
                    for (int p = 0; p < 2; p++)
#pragma unroll
                        for (int q = 0; q < 4; q++) acc[i][j][p][q] = 0.f;

            for (int k = 0; k < 12; k++) {
                uint4 wb[3];
#pragma unroll
                for (int j = 0; j < 3; j++)
                    wb[j] = g_fc1p[((size_t)(chunk * 12 + ctg * 3 + j) * 12 + k) * 32 + lane];
                uint32_t RA[2][4];
#pragma unroll
                for (int i = 0; i < 2; i++)
                    ldsm_x4(RA[i], asbase + i * asrow16 + k * 32);
#pragma unroll
                for (int j = 0; j < 3; j++)
#pragma unroll
                    for (int i = 0; i < 2; i++) {
                        mma_b(acc[i][j][0], RA[i], wb[j].x, wb[j].y);
                        mma_b(acc[i][j][1], RA[i], wb[j].z, wb[j].w);
                    }
            }
            // in-register epilogue: bias + exact GELU + bf16 pack -> midb
#pragma unroll
            for (int j = 0; j < 3; j++)
#pragma unroll
                for (int p = 0; p < 2; p++) {
                    int col = (ctg * 3 + j) * 16 + p * 8 + tig * 2;
                    float b0 = fc1b[chunk * 192 + col];
                    float b1 = fc1b[chunk * 192 + col + 1];
#pragma unroll
                    for (int i = 0; i < 2; i++) {
                        int row = rtg * 32 + i * 16 + gg;
                        float v0 = acc[i][j][p][0] + b0, v1 = acc[i][j][p][1] + b1;
                        float v2 = acc[i][j][p][2] + b0, v3 = acc[i][j][p][3] + b1;
                        float g0 = 0.5f * v0 * (1.f + erff(v0 * 0.70710678118654752f));
                        float g1 = 0.5f * v1 * (1.f + erff(v1 * 0.70710678118654752f));
                        float g2 = 0.5f * v2 * (1.f + erff(v2 * 0.70710678118654752f));
                        float g3 = 0.5f * v3 * (1.f + erff(v3 * 0.70710678118654752f));
                        *(uint32_t*)(midb + row * AS_LD + col)       = pack_b2(g0, g1);
                        *(uint32_t*)(midb + (row + 8) * AS_LD + col) = pack_b2(g2, g3);
                    }
                }
        }
        __syncthreads();

        // GEMM2 partial bf16 mma.sync (B double-buffered), acc2 persistent
        {
            uint4 wb[3];
#pragma unroll
            for (int j = 0; j < 3; j++)
                wb[j] = g_fc2p[((size_t)(ctg * 3 + j) * 48 + chunk * 12) * 32 + lane];
            for (int k = 0; k < 12; k++) {
                uint4 nb[3];
                if (k < 11) {
#pragma unroll
                    for (int j = 0; j < 3; j++)
                        nb[j] = g_fc2p[((size_t)(ctg * 3 + j) * 48 + chunk * 12 + k + 1) * 32 + lane];
                }
                uint32_t RA[2][4];
#pragma unroll
                for (int i = 0; i < 2; i++)
                    ldsm_x4(RA[i], mbbase + i * asrow16 + k * 32);
#pragma unroll
                for (int j = 0; j < 3; j++)
#pragma unroll
                    for (int i = 0; i < 2; i++) {
                        mma_b(acc2[i][j][0], RA[i], wb[j].x, wb[j].y);
                        mma_b(acc2[i][j][1], RA[i], wb[j].z, wb[j].w);
                    }
                if (k < 11) { wb[0] = nb[0]; wb[1] = nb[1]; wb[2] = nb[2]; }
            }
        }
        __syncthreads();
    }

    // ---- store MLP output -> mid ----
#pragma unroll
    for (int i = 0; i < 2; i++)
#pragma unroll
        for (int j = 0; j < 3; j++)
#pragma unroll
            for (int p = 0; p < 2; p++) {
                int col = (ctg * 3 + j) * 16 + p * 8 + tig * 2;
                int row = rtg * 32 + i * 16 + gg;
                *(float2*)(mid + row * MD_LD + col)       = make_float2(acc2[i][j][p][0], acc2[i][j][p][1]);
                *(float2*)(mid + (row + 8) * MD_LD + col) = make_float2(acc2[i][j][p][2], acc2[i][j][p][3]);
            }
    __syncthreads();

    // ---- final pass 1 (c-fast, coalesced g_h1 reads): mid = (mid+h1)+fc2b ----
    for (int idx = tid; idx < 64 * 48; idx += 256) {
        int r = idx / 48, c4 = (idx - r * 48) * 4;
        float4 m  = *(const float4*)(mid + r * MD_LD + c4);
        float4 h  = *(const float4*)(g_h1 + (size_t)(t0 + r) * DIMC + c4);
        float4 bb = *(const float4*)(fc2b + c4);
        m.x = (m.x + h.x) + bb.x;
        m.y = (m.y + h.y) + bb.y;
        m.z = (m.z + h.z) + bb.z;
        m.w = (m.w + h.w) + bb.w;
        *(float4*)(mid + r * MD_LD + c4) = m;
    }
    __syncthreads();

    // ---- final pass 2 (r-fast): coalesced NCHW scatter ----
    for (int idx = tid; idx < 64 * 192; idx += 256) {
        int r = idx & 63;
        int c = idx >> 6;
        int t = t0 + r;
        int win = t / 49; int pos = t - win * 49;
        int b  = win >> 10;
        int wh = (win >> 5) & 31;
        int ww = win & 31;
        int pi = pos / 7;
        int hh = wh * 7 + pi;
        int wx = ww * 7 + (pos - pi * 7);
        out[((size_t)(b * DIMC + c)) * HWSQ + hh * HWI + wx] = mid[r * MD_LD + c];
    }
}

// ============================================================================
extern "C" void kernel_launch(void* const* d_in, const int* in_sizes, int n_in,
                              void* d_out, int out_size)
{
    (void)in_sizes; (void)n_in; (void)out_size;
    const float* x     = (const float*)d_in[0];
    const float* ln1w  = (const float*)d_in[1];
    const float* ln1b  = (const float*)d_in[2];
    const float* qkvw  = (const float*)d_in[3];
    const float* qkvb  = (const float*)d_in[4];
    const float* projw = (const float*)d_in[5];
    const float* projb = (const float*)d_in[6];
    const float* rpb   = (const float*)d_in[7];
    const float* ln2w  = (const float*)d_in[8];
    const float* ln2b  = (const float*)d_in[9];
    const float* fc1w  = (const float*)d_in[10];
    const float* fc1b  = (const float*)d_in[11];
    const float* fc2w  = (const float*)d_in[12];
    const float* fc2b  = (const float*)d_in[13];
    const int*   ridx  = (const int*)  d_in[14];
    float* out = (float*)d_out;

    cudaFuncSetAttribute(qkv_gemm,    cudaFuncAttributeMaxDynamicSharedMemorySize, QKV_SMEM);
    cudaFuncSetAttribute(attn_heads,  cudaFuncAttributeMaxDynamicSharedMemorySize, AH_SMEM);
    cudaFuncSetAttribute(tail_kernel, cudaFuncAttributeMaxDynamicSharedMemorySize, TAIL_SMEM);

    prelude<<<(PRE_TOT + 511) / 512, 512>>>(qkvw, projw, fc1w, fc2w, rpb, ridx);

    qkv_gemm<<<TTOK / 64, 256, QKV_SMEM>>>(x, ln1w, ln1b, qkvb);

    dim3 ag(NWIN, 6);
    attn_heads<<<ag, 128, AH_SMEM>>>();

    tail_kernel<<<TTOK / 64, 256, TAIL_SMEM>>>(x, projb, ln2w, ln2b, fc1b, fc2b, out);
}